// round 4
// baseline (speedup 1.0000x reference)
#include <cuda_runtime.h>
#include <cstdint>

#define DG 128
#define MAXN 100000
#define MAXE 1600000

// Scratch (device globals — no allocation allowed).
__device__ int g_deg[MAXN];
__device__ int g_rowptr[MAXN + 1];
__device__ int g_cursor[MAXN];
__device__ int g_csrc[MAXE];
__device__ __align__(16) float g_h[MAXN * DG];    // h after layer0 + LN
__device__ __align__(16) float g_agg[MAXN * DG];  // layer1 mean-agg (inv_deg applied)

// ---------------------------------------------------------------------------
// CSR build: zero deg -> histogram -> 1-block scan -> fill (sorted by dst)
// ---------------------------------------------------------------------------
__global__ void zero_deg_kernel(int n) {
    int i = blockIdx.x * blockDim.x + threadIdx.x;
    if (i < n) g_deg[i] = 0;
}

__global__ void hist_kernel(const int* __restrict__ ei, int nE) {
    int e = blockIdx.x * blockDim.x + threadIdx.x;
    if (e < nE) atomicAdd(&g_deg[ei[nE + e]], 1);
}

__global__ __launch_bounds__(1024) void scan_kernel(int n) {
    int t = threadIdx.x;
    int lane = t & 31, wid = t >> 5;
    int per = (n + 1023) >> 10;
    int start = t * per;
    int end = start + per; if (end > n) end = n;
    int s = 0;
    for (int i = start; i < end; i++) s += g_deg[i];
    int val = s;
#pragma unroll
    for (int o = 1; o < 32; o <<= 1) {
        int u = __shfl_up_sync(0xffffffffu, val, o);
        if (lane >= o) val += u;
    }
    __shared__ int wsum[32];
    if (lane == 31) wsum[wid] = val;
    __syncthreads();
    if (wid == 0) {
        int w = wsum[lane];
#pragma unroll
        for (int o = 1; o < 32; o <<= 1) {
            int u = __shfl_up_sync(0xffffffffu, w, o);
            if (lane >= o) w += u;
        }
        wsum[lane] = w;
    }
    __syncthreads();
    int base = val - s + (wid ? wsum[wid - 1] : 0);  // exclusive prefix
    int run = base;
    for (int i = start; i < end; i++) {
        g_rowptr[i] = run;
        g_cursor[i] = run;
        run += g_deg[i];
    }
    if (end == n) g_rowptr[n] = run;  // trailing threads also write total (same value)
}

__global__ void fill_kernel(const int* __restrict__ ei, int nE) {
    int e = blockIdx.x * blockDim.x + threadIdx.x;
    if (e >= nE) return;
    int s = ei[e];
    int d = ei[nE + e];
    int pos = atomicAdd(&g_cursor[d], 1);
    g_csrc[pos] = s;
}

// ---------------------------------------------------------------------------
// Layer 0 (fused): warp per node. Gather x[src] over in-edges (mean), then
// 3->128 linear (Wl on agg, Wr on own x) + bias + ReLU + LayerNorm, all
// within one warp (each lane owns 4 of 128 dims). No atomics, no block sync.
// ---------------------------------------------------------------------------
__device__ __forceinline__ float warp_sum(float v) {
#pragma unroll
    for (int o = 16; o; o >>= 1) v += __shfl_xor_sync(0xffffffffu, v, o);
    return v;
}

__global__ __launch_bounds__(256) void layer0_kernel(
    const float* __restrict__ x, const float* __restrict__ Wl,
    const float* __restrict__ Wr, const float* __restrict__ b,
    const float* __restrict__ g, const float* __restrict__ be, int n) {
    int w = (blockIdx.x * blockDim.x + threadIdx.x) >> 5;
    if (w >= n) return;
    int lane = threadIdx.x & 31;
    int r0 = g_rowptr[w], r1 = g_rowptr[w + 1];

    float a0 = 0.f, a1 = 0.f, a2 = 0.f;
    for (int j = r0 + lane; j < r1; j += 32) {
        int s = g_csrc[j];
        a0 += x[3 * s];
        a1 += x[3 * s + 1];
        a2 += x[3 * s + 2];
    }
    a0 = warp_sum(a0); a1 = warp_sum(a1); a2 = warp_sum(a2);
    float inv = 1.f / fmaxf((float)(r1 - r0), 1.f);
    a0 *= inv; a1 *= inv; a2 *= inv;

    float x0 = x[3 * w], x1 = x[3 * w + 1], x2 = x[3 * w + 2];

    int col = lane * 4;
    float4 wl0 = *(const float4*)&Wl[0 * DG + col];
    float4 wl1 = *(const float4*)&Wl[1 * DG + col];
    float4 wl2 = *(const float4*)&Wl[2 * DG + col];
    float4 wr0 = *(const float4*)&Wr[0 * DG + col];
    float4 wr1 = *(const float4*)&Wr[1 * DG + col];
    float4 wr2 = *(const float4*)&Wr[2 * DG + col];
    float4 bv  = *(const float4*)&b[col];

    float v0 = bv.x + a0 * wl0.x + a1 * wl1.x + a2 * wl2.x + x0 * wr0.x + x1 * wr1.x + x2 * wr2.x;
    float v1 = bv.y + a0 * wl0.y + a1 * wl1.y + a2 * wl2.y + x0 * wr0.y + x1 * wr1.y + x2 * wr2.y;
    float v2 = bv.z + a0 * wl0.z + a1 * wl1.z + a2 * wl2.z + x0 * wr0.z + x1 * wr1.z + x2 * wr2.z;
    float v3 = bv.w + a0 * wl0.w + a1 * wl1.w + a2 * wl2.w + x0 * wr0.w + x1 * wr1.w + x2 * wr2.w;
    v0 = fmaxf(v0, 0.f); v1 = fmaxf(v1, 0.f); v2 = fmaxf(v2, 0.f); v3 = fmaxf(v3, 0.f);

    float mu = warp_sum(v0 + v1 + v2 + v3) * (1.f / DG);
    float d0 = v0 - mu, d1 = v1 - mu, d2 = v2 - mu, d3 = v3 - mu;
    float var = warp_sum(d0 * d0 + d1 * d1 + d2 * d2 + d3 * d3) * (1.f / DG);
    float rs = rsqrtf(var + 1e-5f);

    float4 gv = *(const float4*)&g[col];
    float4 bev = *(const float4*)&be[col];
    float4 o;
    o.x = d0 * rs * gv.x + bev.x;
    o.y = d1 * rs * gv.y + bev.y;
    o.z = d2 * rs * gv.z + bev.z;
    o.w = d3 * rs * gv.w + bev.w;
    *(float4*)&g_h[(size_t)w * DG + col] = o;
}

// ---------------------------------------------------------------------------
// Layer 1 aggregation: warp per dst node, register accumulation, 4-way
// unrolled gather over in-edges (g_h is L2-resident). No atomics, no zeroing.
// inv_deg applied here.
// ---------------------------------------------------------------------------
__global__ __launch_bounds__(256) void agg_kernel(int n) {
    int w = (blockIdx.x * blockDim.x + threadIdx.x) >> 5;
    if (w >= n) return;
    int lane = threadIdx.x & 31;
    int r0 = g_rowptr[w], r1 = g_rowptr[w + 1];
    size_t co = (size_t)lane * 4;

    float ax = 0.f, ay = 0.f, az = 0.f, aw = 0.f;
    int j = r0;
    for (; j + 4 <= r1; j += 4) {
        int s0 = g_csrc[j], s1 = g_csrc[j + 1], s2 = g_csrc[j + 2], s3 = g_csrc[j + 3];
        float4 v0 = *(const float4*)(g_h + (size_t)s0 * DG + co);
        float4 v1 = *(const float4*)(g_h + (size_t)s1 * DG + co);
        float4 v2 = *(const float4*)(g_h + (size_t)s2 * DG + co);
        float4 v3 = *(const float4*)(g_h + (size_t)s3 * DG + co);
        ax += v0.x + v1.x + v2.x + v3.x;
        ay += v0.y + v1.y + v2.y + v3.y;
        az += v0.z + v1.z + v2.z + v3.z;
        aw += v0.w + v1.w + v2.w + v3.w;
    }
    for (; j < r1; j++) {
        int s = g_csrc[j];
        float4 v = *(const float4*)(g_h + (size_t)s * DG + co);
        ax += v.x; ay += v.y; az += v.z; aw += v.w;
    }
    float inv = 1.f / fmaxf((float)(r1 - r0), 1.f);
    float4 o = make_float4(ax * inv, ay * inv, az * inv, aw * inv);
    *(float4*)(g_agg + (size_t)w * DG + co) = o;
}

// ---------------------------------------------------------------------------
// Layer 1 output GEMM + relu.
// Block tile: 64 nodes x 128 cols, 128 threads, each thread 8 rows x 8 cols.
// out[n,j] = relu( agg[n] @ Wl1 + h[n] @ Wr1 + b1 )
// ---------------------------------------------------------------------------
#define KC 16
__global__ __launch_bounds__(128) void out_kernel(
    const float* __restrict__ Wl, const float* __restrict__ Wr,
    const float* __restrict__ b1, float* __restrict__ out, int n) {
    __shared__ __align__(16) float sWl[KC][DG], sWr[KC][DG];
    __shared__ __align__(16) float sA[64][KC + 1], sH[64][KC + 1];

    int tid = threadIdx.x;
    int n0 = blockIdx.x * 64;
    int rg = tid >> 4;
    int cg = tid & 15;
    int r0 = rg * 8;

    float4 acc0[8], acc1[8];
#pragma unroll
    for (int i = 0; i < 8; i++) {
        acc0[i] = make_float4(0.f, 0.f, 0.f, 0.f);
        acc1[i] = make_float4(0.f, 0.f, 0.f, 0.f);
    }

    int lnode = tid >> 1;
    int lhalf = tid & 1;
    bool lact = (n0 + lnode) < n;

    for (int kc = 0; kc < DG; kc += KC) {
        __syncthreads();
#pragma unroll
        for (int q = 0; q < 4; q++) {
            int idx = tid + q * 128;
            int kr = idx >> 5;
            int cc = (idx & 31) * 4;
            *(float4*)&sWl[kr][cc] = *(const float4*)&Wl[(size_t)(kc + kr) * DG + cc];
            *(float4*)&sWr[kr][cc] = *(const float4*)&Wr[(size_t)(kc + kr) * DG + cc];
        }
#pragma unroll
        for (int q = 0; q < 2; q++) {
            int kk = lhalf * 8 + q * 4;
            float4 av = make_float4(0.f, 0.f, 0.f, 0.f);
            float4 hv = make_float4(0.f, 0.f, 0.f, 0.f);
            if (lact) {
                av = *(const float4*)&g_agg[(size_t)(n0 + lnode) * DG + kc + kk];
                hv = *(const float4*)&g_h[(size_t)(n0 + lnode) * DG + kc + kk];
            }
            sA[lnode][kk + 0] = av.x; sA[lnode][kk + 1] = av.y;
            sA[lnode][kk + 2] = av.z; sA[lnode][kk + 3] = av.w;
            sH[lnode][kk + 0] = hv.x; sH[lnode][kk + 1] = hv.y;
            sH[lnode][kk + 2] = hv.z; sH[lnode][kk + 3] = hv.w;
        }
        __syncthreads();

#pragma unroll
        for (int k = 0; k < KC; k++) {
            float4 wl0 = *(float4*)&sWl[k][cg * 4];
            float4 wl1 = *(float4*)&sWl[k][64 + cg * 4];
            float4 wr0 = *(float4*)&sWr[k][cg * 4];
            float4 wr1 = *(float4*)&sWr[k][64 + cg * 4];
#pragma unroll
            for (int i = 0; i < 8; i++) {
                float a = sA[r0 + i][k];
                float h = sH[r0 + i][k];
                acc0[i].x += a * wl0.x + h * wr0.x;
                acc0[i].y += a * wl0.y + h * wr0.y;
                acc0[i].z += a * wl0.z + h * wr0.z;
                acc0[i].w += a * wl0.w + h * wr0.w;
                acc1[i].x += a * wl1.x + h * wr1.x;
                acc1[i].y += a * wl1.y + h * wr1.y;
                acc1[i].z += a * wl1.z + h * wr1.z;
                acc1[i].w += a * wl1.w + h * wr1.w;
            }
        }
    }

    float4 bv0 = *(const float4*)&b1[cg * 4];
    float4 bv1 = *(const float4*)&b1[64 + cg * 4];
#pragma unroll
    for (int i = 0; i < 8; i++) {
        int node = n0 + r0 + i;
        if (node < n) {
            float4 o;
            o.x = fmaxf(acc0[i].x + bv0.x, 0.f);
            o.y = fmaxf(acc0[i].y + bv0.y, 0.f);
            o.z = fmaxf(acc0[i].z + bv0.z, 0.f);
            o.w = fmaxf(acc0[i].w + bv0.w, 0.f);
            *(float4*)&out[(size_t)node * DG + cg * 4] = o;
            o.x = fmaxf(acc1[i].x + bv1.x, 0.f);
            o.y = fmaxf(acc1[i].y + bv1.y, 0.f);
            o.z = fmaxf(acc1[i].z + bv1.z, 0.f);
            o.w = fmaxf(acc1[i].w + bv1.w, 0.f);
            *(float4*)&out[(size_t)node * DG + 64 + cg * 4] = o;
        }
    }
}

// ---------------------------------------------------------------------------
extern "C" void kernel_launch(void* const* d_in, const int* in_sizes, int n_in,
                              void* d_out, int out_size) {
    const float* x   = (const float*)d_in[0];
    const int*   ei  = (const int*)d_in[1];
    const float* Wl0 = (const float*)d_in[2];
    const float* Wr0 = (const float*)d_in[3];
    const float* b0  = (const float*)d_in[4];
    const float* Wl1 = (const float*)d_in[5];
    const float* Wr1 = (const float*)d_in[6];
    const float* b1  = (const float*)d_in[7];
    const float* g   = (const float*)d_in[8];
    const float* be  = (const float*)d_in[9];
    float* out = (float*)d_out;

    int n  = in_sizes[0] / 3;
    int nE = in_sizes[1] / 2;

    zero_deg_kernel<<<(n + 255) / 256, 256>>>(n);
    hist_kernel<<<(nE + 255) / 256, 256>>>(ei, nE);
    scan_kernel<<<1, 1024>>>(n);
    fill_kernel<<<(nE + 255) / 256, 256>>>(ei, nE);
    int warps = n;
    int blocks = (warps * 32 + 255) / 256;
    layer0_kernel<<<blocks, 256>>>(x, Wl0, Wr0, b0, g, be, n);
    agg_kernel<<<blocks, 256>>>(n);
    out_kernel<<<(n + 63) / 64, 128>>>(Wl1, Wr1, b1, out, n);
}

// round 5
// speedup vs baseline: 1.1856x; 1.1856x over previous
#include <cuda_runtime.h>
#include <cstdint>

#define DG 128
#define MAXN 100000
#define MAXE 1600000

// Scratch (device globals — no allocation allowed).
__device__ int g_deg[MAXN];
__device__ int g_rowptr[MAXN + 1];
__device__ int g_cursor[MAXN];
__device__ int g_csrc[MAXE];
__device__ __align__(16) float g_h[MAXN * DG];    // h after layer0 + LN
__device__ __align__(16) float g_agg[MAXN * DG];  // layer1 mean-agg (inv_deg applied)

// ---------------------------------------------------------------------------
// CSR build: zero deg -> histogram -> 1-block scan -> fill (sorted by dst)
// ---------------------------------------------------------------------------
__global__ void zero_deg_kernel(int n) {
    int i = blockIdx.x * blockDim.x + threadIdx.x;
    if (i < n) g_deg[i] = 0;
}

__global__ void hist_kernel(const int* __restrict__ ei, int nE) {
    int e = blockIdx.x * blockDim.x + threadIdx.x;
    if (e < nE) atomicAdd(&g_deg[ei[nE + e]], 1);
}

__global__ __launch_bounds__(1024) void scan_kernel(int n) {
    int t = threadIdx.x;
    int lane = t & 31, wid = t >> 5;
    int per = (n + 1023) >> 10;
    int start = t * per;
    int end = start + per; if (end > n) end = n;
    int s = 0;
    for (int i = start; i < end; i++) s += g_deg[i];
    int val = s;
#pragma unroll
    for (int o = 1; o < 32; o <<= 1) {
        int u = __shfl_up_sync(0xffffffffu, val, o);
        if (lane >= o) val += u;
    }
    __shared__ int wsum[32];
    if (lane == 31) wsum[wid] = val;
    __syncthreads();
    if (wid == 0) {
        int w = wsum[lane];
#pragma unroll
        for (int o = 1; o < 32; o <<= 1) {
            int u = __shfl_up_sync(0xffffffffu, w, o);
            if (lane >= o) w += u;
        }
        wsum[lane] = w;
    }
    __syncthreads();
    int base = val - s + (wid ? wsum[wid - 1] : 0);  // exclusive prefix
    int run = base;
    for (int i = start; i < end; i++) {
        g_rowptr[i] = run;
        g_cursor[i] = run;
        run += g_deg[i];
    }
    if (end == n) g_rowptr[n] = run;
}

__global__ void fill_kernel(const int* __restrict__ ei, int nE) {
    int e = blockIdx.x * blockDim.x + threadIdx.x;
    if (e >= nE) return;
    int s = ei[e];
    int d = ei[nE + e];
    int pos = atomicAdd(&g_cursor[d], 1);
    g_csrc[pos] = s;
}

// ---------------------------------------------------------------------------
// Layer 0 (fused): warp per node. Gather x[src] (mean), 3->128 linear + bias
// + ReLU + LayerNorm, all in-warp.
// ---------------------------------------------------------------------------
__device__ __forceinline__ float warp_sum(float v) {
#pragma unroll
    for (int o = 16; o; o >>= 1) v += __shfl_xor_sync(0xffffffffu, v, o);
    return v;
}

__global__ __launch_bounds__(256) void layer0_kernel(
    const float* __restrict__ x, const float* __restrict__ Wl,
    const float* __restrict__ Wr, const float* __restrict__ b,
    const float* __restrict__ g, const float* __restrict__ be, int n) {
    int w = (blockIdx.x * blockDim.x + threadIdx.x) >> 5;
    if (w >= n) return;
    int lane = threadIdx.x & 31;
    int r0 = g_rowptr[w], r1 = g_rowptr[w + 1];

    float a0 = 0.f, a1 = 0.f, a2 = 0.f;
    for (int j = r0 + lane; j < r1; j += 32) {
        int s = g_csrc[j];
        a0 += x[3 * s];
        a1 += x[3 * s + 1];
        a2 += x[3 * s + 2];
    }
    a0 = warp_sum(a0); a1 = warp_sum(a1); a2 = warp_sum(a2);
    float inv = 1.f / fmaxf((float)(r1 - r0), 1.f);
    a0 *= inv; a1 *= inv; a2 *= inv;

    float x0 = x[3 * w], x1 = x[3 * w + 1], x2 = x[3 * w + 2];

    int col = lane * 4;
    float4 wl0 = *(const float4*)&Wl[0 * DG + col];
    float4 wl1 = *(const float4*)&Wl[1 * DG + col];
    float4 wl2 = *(const float4*)&Wl[2 * DG + col];
    float4 wr0 = *(const float4*)&Wr[0 * DG + col];
    float4 wr1 = *(const float4*)&Wr[1 * DG + col];
    float4 wr2 = *(const float4*)&Wr[2 * DG + col];
    float4 bv  = *(const float4*)&b[col];

    float v0 = bv.x + a0 * wl0.x + a1 * wl1.x + a2 * wl2.x + x0 * wr0.x + x1 * wr1.x + x2 * wr2.x;
    float v1 = bv.y + a0 * wl0.y + a1 * wl1.y + a2 * wl2.y + x0 * wr0.y + x1 * wr1.y + x2 * wr2.y;
    float v2 = bv.z + a0 * wl0.z + a1 * wl1.z + a2 * wl2.z + x0 * wr0.z + x1 * wr1.z + x2 * wr2.z;
    float v3 = bv.w + a0 * wl0.w + a1 * wl1.w + a2 * wl2.w + x0 * wr0.w + x1 * wr1.w + x2 * wr2.w;
    v0 = fmaxf(v0, 0.f); v1 = fmaxf(v1, 0.f); v2 = fmaxf(v2, 0.f); v3 = fmaxf(v3, 0.f);

    float mu = warp_sum(v0 + v1 + v2 + v3) * (1.f / DG);
    float d0 = v0 - mu, d1 = v1 - mu, d2 = v2 - mu, d3 = v3 - mu;
    float var = warp_sum(d0 * d0 + d1 * d1 + d2 * d2 + d3 * d3) * (1.f / DG);
    float rs = rsqrtf(var + 1e-5f);

    float4 gv = *(const float4*)&g[col];
    float4 bev = *(const float4*)&be[col];
    float4 o;
    o.x = d0 * rs * gv.x + bev.x;
    o.y = d1 * rs * gv.y + bev.y;
    o.z = d2 * rs * gv.z + bev.z;
    o.w = d3 * rs * gv.w + bev.w;
    *(float4*)&g_h[(size_t)w * DG + col] = o;
}

// ---------------------------------------------------------------------------
// Layer 1 aggregation: warp per dst node, register accumulation, 4-way
// unrolled gather over in-edges. inv_deg applied here.
// ---------------------------------------------------------------------------
__global__ __launch_bounds__(256) void agg_kernel(int n) {
    int w = (blockIdx.x * blockDim.x + threadIdx.x) >> 5;
    if (w >= n) return;
    int lane = threadIdx.x & 31;
    int r0 = g_rowptr[w], r1 = g_rowptr[w + 1];
    size_t co = (size_t)lane * 4;

    float ax = 0.f, ay = 0.f, az = 0.f, aw = 0.f;
    int j = r0;
    for (; j + 4 <= r1; j += 4) {
        int s0 = g_csrc[j], s1 = g_csrc[j + 1], s2 = g_csrc[j + 2], s3 = g_csrc[j + 3];
        float4 v0 = *(const float4*)(g_h + (size_t)s0 * DG + co);
        float4 v1 = *(const float4*)(g_h + (size_t)s1 * DG + co);
        float4 v2 = *(const float4*)(g_h + (size_t)s2 * DG + co);
        float4 v3 = *(const float4*)(g_h + (size_t)s3 * DG + co);
        ax += v0.x + v1.x + v2.x + v3.x;
        ay += v0.y + v1.y + v2.y + v3.y;
        az += v0.z + v1.z + v2.z + v3.z;
        aw += v0.w + v1.w + v2.w + v3.w;
    }
    for (; j < r1; j++) {
        int s = g_csrc[j];
        float4 v = *(const float4*)(g_h + (size_t)s * DG + co);
        ax += v.x; ay += v.y; az += v.z; aw += v.w;
    }
    float inv = 1.f / fmaxf((float)(r1 - r0), 1.f);
    float4 o = make_float4(ax * inv, ay * inv, az * inv, aw * inv);
    *(float4*)(g_agg + (size_t)w * DG + co) = o;
}

// ---------------------------------------------------------------------------
// Layer 1 output GEMM + relu, TF32 tensor cores (mma.sync m16n8k8).
// out[m, :] = relu( [agg | h][m, :] @ [Wl ; Wr] + b1 ),  K = 256.
// Block: 128 threads = 4 warps (2x2). Tile M=64, N=128. K chunked by 32.
// ---------------------------------------------------------------------------
__device__ __forceinline__ float to_tf32(float x) {
    float r;
    asm("cvt.rna.tf32.f32 %0, %1;" : "=f"(r) : "f"(x));
    return r;
}

#define KB 32
__global__ __launch_bounds__(128) void out_kernel(
    const float* __restrict__ Wl, const float* __restrict__ Wr,
    const float* __restrict__ bias, float* __restrict__ out, int n) {
    // pads chosen so fragment loads are bank-conflict-free:
    // sA addr = 36*row + k -> (4*row + k) mod 32 distinct over 8 rows x 4 k
    // sB addr = 136*k + n  -> (8*k + n) mod 32 distinct over 4 k x 8 n
    __shared__ float sA[64][36];
    __shared__ float sB[KB][136];

    int tid = threadIdx.x;
    int wid = tid >> 5;
    int lane = tid & 31;
    int wm = wid >> 1;        // 0..1 : rows wm*32 .. +31
    int wn = wid & 1;         // 0..1 : cols wn*64 .. +63
    int gid = lane >> 2;      // 0..7
    int tg = lane & 3;        // 0..3
    int n0 = blockIdx.x * 64;

    float acc[2][8][4];
#pragma unroll
    for (int mt = 0; mt < 2; mt++)
#pragma unroll
        for (int nt = 0; nt < 8; nt++)
#pragma unroll
            for (int i = 0; i < 4; i++) acc[mt][nt][i] = 0.f;

    // A staging map: row = tid>>1 (0..63), kpart = (tid&1)*16
    int arow = tid >> 1;
    int akp = (tid & 1) * 16;
    bool aact = (n0 + arow) < n;
    // B staging map: k = tid>>2 (0..31), nbase = (tid&3)*32
    int bk = tid >> 2;
    int bnb = (tid & 3) * 32;

    for (int kc = 0; kc < 2 * DG; kc += KB) {
        __syncthreads();
        // ---- stage A (64 x 32) ----
        {
            const float* src = (kc < DG) ? g_agg : g_h;
            int kadj = kc & (DG - 1);
#pragma unroll
            for (int q = 0; q < 4; q++) {
                float4 v = make_float4(0.f, 0.f, 0.f, 0.f);
                if (aact)
                    v = *(const float4*)&src[(size_t)(n0 + arow) * DG + kadj + akp + q * 4];
                int kk = akp + q * 4;
                sA[arow][kk + 0] = to_tf32(v.x);
                sA[arow][kk + 1] = to_tf32(v.y);
                sA[arow][kk + 2] = to_tf32(v.z);
                sA[arow][kk + 3] = to_tf32(v.w);
            }
        }
        // ---- stage B (32 x 128) ----
        {
            const float* W = (kc < DG) ? Wl : Wr;
            int kadj = (kc & (DG - 1)) + bk;
#pragma unroll
            for (int q = 0; q < 8; q++) {
                float4 v = *(const float4*)&W[(size_t)kadj * DG + bnb + q * 4];
                int nn = bnb + q * 4;
                sB[bk][nn + 0] = to_tf32(v.x);
                sB[bk][nn + 1] = to_tf32(v.y);
                sB[bk][nn + 2] = to_tf32(v.z);
                sB[bk][nn + 3] = to_tf32(v.w);
            }
        }
        __syncthreads();

        // ---- compute: 4 k8-steps ----
#pragma unroll
        for (int ks = 0; ks < KB; ks += 8) {
            uint32_t bf[8][2];
#pragma unroll
            for (int nt = 0; nt < 8; nt++) {
                int ncol = wn * 64 + nt * 8 + gid;
                bf[nt][0] = __float_as_uint(sB[ks + tg][ncol]);
                bf[nt][1] = __float_as_uint(sB[ks + tg + 4][ncol]);
            }
#pragma unroll
            for (int mt = 0; mt < 2; mt++) {
                int r = wm * 32 + mt * 16 + gid;
                uint32_t af0 = __float_as_uint(sA[r][ks + tg]);
                uint32_t af1 = __float_as_uint(sA[r + 8][ks + tg]);
                uint32_t af2 = __float_as_uint(sA[r][ks + tg + 4]);
                uint32_t af3 = __float_as_uint(sA[r + 8][ks + tg + 4]);
#pragma unroll
                for (int nt = 0; nt < 8; nt++) {
                    asm volatile(
                        "mma.sync.aligned.m16n8k8.row.col.f32.tf32.tf32.f32 "
                        "{%0,%1,%2,%3}, {%4,%5,%6,%7}, {%8,%9}, {%0,%1,%2,%3};"
                        : "+f"(acc[mt][nt][0]), "+f"(acc[mt][nt][1]),
                          "+f"(acc[mt][nt][2]), "+f"(acc[mt][nt][3])
                        : "r"(af0), "r"(af1), "r"(af2), "r"(af3),
                          "r"(bf[nt][0]), "r"(bf[nt][1]));
                }
            }
        }
    }

    // ---- epilogue: bias + relu, float2 stores (c0/c1 adjacent cols) ----
#pragma unroll
    for (int nt = 0; nt < 8; nt++) {
        int col = wn * 64 + nt * 8 + 2 * tg;
        float2 bv = *(const float2*)&bias[col];
#pragma unroll
        for (int mt = 0; mt < 2; mt++) {
            int row = n0 + wm * 32 + mt * 16 + gid;
            if (row < n) {
                float2 o;
                o.x = fmaxf(acc[mt][nt][0] + bv.x, 0.f);
                o.y = fmaxf(acc[mt][nt][1] + bv.y, 0.f);
                *(float2*)&out[(size_t)row * DG + col] = o;
            }
            if (row + 8 < n) {
                float2 o;
                o.x = fmaxf(acc[mt][nt][2] + bv.x, 0.f);
                o.y = fmaxf(acc[mt][nt][3] + bv.y, 0.f);
                *(float2*)&out[(size_t)(row + 8) * DG + col] = o;
            }
        }
    }
}

// ---------------------------------------------------------------------------
extern "C" void kernel_launch(void* const* d_in, const int* in_sizes, int n_in,
                              void* d_out, int out_size) {
    const float* x   = (const float*)d_in[0];
    const int*   ei  = (const int*)d_in[1];
    const float* Wl0 = (const float*)d_in[2];
    const float* Wr0 = (const float*)d_in[3];
    const float* b0  = (const float*)d_in[4];
    const float* Wl1 = (const float*)d_in[5];
    const float* Wr1 = (const float*)d_in[6];
    const float* b1  = (const float*)d_in[7];
    const float* g   = (const float*)d_in[8];
    const float* be  = (const float*)d_in[9];
    float* out = (float*)d_out;

    int n  = in_sizes[0] / 3;
    int nE = in_sizes[1] / 2;

    zero_deg_kernel<<<(n + 255) / 256, 256>>>(n);
    hist_kernel<<<(nE + 255) / 256, 256>>>(ei, nE);
    scan_kernel<<<1, 1024>>>(n);
    fill_kernel<<<(nE + 255) / 256, 256>>>(ei, nE);
    int blocks = (n * 32 + 255) / 256;
    layer0_kernel<<<blocks, 256>>>(x, Wl0, Wr0, b0, g, be, n);
    agg_kernel<<<blocks, 256>>>(n);
    out_kernel<<<(n + 63) / 64, 128>>>(Wl1, Wr1, b1, out, n);
}

// round 6
// speedup vs baseline: 1.2047x; 1.0162x over previous
#include <cuda_runtime.h>
#include <cuda_fp16.h>
#include <cstdint>

#define DG 128
#define MAXN 100000
#define MAXE 1600000

// Scratch (device globals — no allocation allowed).
__device__ int g_deg[MAXN];
__device__ int g_rowptr[MAXN + 1];
__device__ int g_cursor[MAXN];
__device__ int g_csrc[MAXE];
__device__ __align__(16) float g_h[MAXN * DG];     // h after layer0 + LN (fp32)
__device__ __align__(16) __half g_hh[MAXN * DG];   // same h in fp16 (gather path)
__device__ __align__(16) float g_agg[MAXN * DG];   // layer1 mean-agg (fp32)

// ---------------------------------------------------------------------------
// CSR build: zero deg -> histogram -> 1-block scan -> fill (sorted by dst)
// ---------------------------------------------------------------------------
__global__ void zero_deg_kernel(int n) {
    int i = blockIdx.x * blockDim.x + threadIdx.x;
    if (i < n) g_deg[i] = 0;
}

__global__ void hist_kernel(const int* __restrict__ ei, int nE) {
    int e = blockIdx.x * blockDim.x + threadIdx.x;
    if (e < nE) atomicAdd(&g_deg[ei[nE + e]], 1);
}

__global__ __launch_bounds__(1024) void scan_kernel(int n) {
    int t = threadIdx.x;
    int lane = t & 31, wid = t >> 5;
    int per = (n + 1023) >> 10;
    int start = t * per;
    int end = start + per; if (end > n) end = n;
    int s = 0;
    for (int i = start; i < end; i++) s += g_deg[i];
    int val = s;
#pragma unroll
    for (int o = 1; o < 32; o <<= 1) {
        int u = __shfl_up_sync(0xffffffffu, val, o);
        if (lane >= o) val += u;
    }
    __shared__ int wsum[32];
    if (lane == 31) wsum[wid] = val;
    __syncthreads();
    if (wid == 0) {
        int w = wsum[lane];
#pragma unroll
        for (int o = 1; o < 32; o <<= 1) {
            int u = __shfl_up_sync(0xffffffffu, w, o);
            if (lane >= o) w += u;
        }
        wsum[lane] = w;
    }
    __syncthreads();
    int base = val - s + (wid ? wsum[wid - 1] : 0);  // exclusive prefix
    int run = base;
    for (int i = start; i < end; i++) {
        g_rowptr[i] = run;
        g_cursor[i] = run;
        run += g_deg[i];
    }
    if (end == n) g_rowptr[n] = run;
}

__global__ void fill_kernel(const int* __restrict__ ei, int nE) {
    int e = blockIdx.x * blockDim.x + threadIdx.x;
    if (e >= nE) return;
    int s = ei[e];
    int d = ei[nE + e];
    int pos = atomicAdd(&g_cursor[d], 1);
    g_csrc[pos] = s;
}

// ---------------------------------------------------------------------------
// Layer 0 (fused): warp per node. Gather x[src] (mean), 3->128 linear + bias
// + ReLU + LayerNorm, all in-warp. Emits h in fp32 AND fp16.
// ---------------------------------------------------------------------------
__device__ __forceinline__ float warp_sum(float v) {
#pragma unroll
    for (int o = 16; o; o >>= 1) v += __shfl_xor_sync(0xffffffffu, v, o);
    return v;
}

__global__ __launch_bounds__(256) void layer0_kernel(
    const float* __restrict__ x, const float* __restrict__ Wl,
    const float* __restrict__ Wr, const float* __restrict__ b,
    const float* __restrict__ g, const float* __restrict__ be, int n) {
    int w = (blockIdx.x * blockDim.x + threadIdx.x) >> 5;
    if (w >= n) return;
    int lane = threadIdx.x & 31;
    int r0 = g_rowptr[w], r1 = g_rowptr[w + 1];

    float a0 = 0.f, a1 = 0.f, a2 = 0.f;
    for (int j = r0 + lane; j < r1; j += 32) {
        int s = g_csrc[j];
        a0 += x[3 * s];
        a1 += x[3 * s + 1];
        a2 += x[3 * s + 2];
    }
    a0 = warp_sum(a0); a1 = warp_sum(a1); a2 = warp_sum(a2);
    float inv = 1.f / fmaxf((float)(r1 - r0), 1.f);
    a0 *= inv; a1 *= inv; a2 *= inv;

    float x0 = x[3 * w], x1 = x[3 * w + 1], x2 = x[3 * w + 2];

    int col = lane * 4;
    float4 wl0 = *(const float4*)&Wl[0 * DG + col];
    float4 wl1 = *(const float4*)&Wl[1 * DG + col];
    float4 wl2 = *(const float4*)&Wl[2 * DG + col];
    float4 wr0 = *(const float4*)&Wr[0 * DG + col];
    float4 wr1 = *(const float4*)&Wr[1 * DG + col];
    float4 wr2 = *(const float4*)&Wr[2 * DG + col];
    float4 bv  = *(const float4*)&b[col];

    float v0 = bv.x + a0 * wl0.x + a1 * wl1.x + a2 * wl2.x + x0 * wr0.x + x1 * wr1.x + x2 * wr2.x;
    float v1 = bv.y + a0 * wl0.y + a1 * wl1.y + a2 * wl2.y + x0 * wr0.y + x1 * wr1.y + x2 * wr2.y;
    float v2 = bv.z + a0 * wl0.z + a1 * wl1.z + a2 * wl2.z + x0 * wr0.z + x1 * wr1.z + x2 * wr2.z;
    float v3 = bv.w + a0 * wl0.w + a1 * wl1.w + a2 * wl2.w + x0 * wr0.w + x1 * wr1.w + x2 * wr2.w;
    v0 = fmaxf(v0, 0.f); v1 = fmaxf(v1, 0.f); v2 = fmaxf(v2, 0.f); v3 = fmaxf(v3, 0.f);

    float mu = warp_sum(v0 + v1 + v2 + v3) * (1.f / DG);
    float d0 = v0 - mu, d1 = v1 - mu, d2 = v2 - mu, d3 = v3 - mu;
    float var = warp_sum(d0 * d0 + d1 * d1 + d2 * d2 + d3 * d3) * (1.f / DG);
    float rs = rsqrtf(var + 1e-5f);

    float4 gv = *(const float4*)&g[col];
    float4 bev = *(const float4*)&be[col];
    float4 o;
    o.x = d0 * rs * gv.x + bev.x;
    o.y = d1 * rs * gv.y + bev.y;
    o.z = d2 * rs * gv.z + bev.z;
    o.w = d3 * rs * gv.w + bev.w;
    *(float4*)&g_h[(size_t)w * DG + col] = o;
    // fp16 copy for the aggregation gather
    half2 p0 = __floats2half2_rn(o.x, o.y);
    half2 p1 = __floats2half2_rn(o.z, o.w);
    uint2 pk = make_uint2(*(uint32_t*)&p0, *(uint32_t*)&p1);
    *(uint2*)(g_hh + (size_t)w * DG + col) = pk;
}

// ---------------------------------------------------------------------------
// Layer 1 aggregation: warp per dst node, fp16 gather (half the L2 traffic),
// fp32 accumulate, 8-way unrolled for MLP. inv_deg applied here.
// ---------------------------------------------------------------------------
__global__ __launch_bounds__(256) void agg_kernel(int n) {
    int w = (blockIdx.x * blockDim.x + threadIdx.x) >> 5;
    if (w >= n) return;
    int lane = threadIdx.x & 31;
    int r0 = g_rowptr[w], r1 = g_rowptr[w + 1];
    const uint2* hh = (const uint2*)g_hh;   // 32 uint2 per node row

    float ax = 0.f, ay = 0.f, az = 0.f, aw = 0.f;
    int j = r0;
    for (; j + 8 <= r1; j += 8) {
        uint2 u[8];
#pragma unroll
        for (int q = 0; q < 8; q++) {
            int s = g_csrc[j + q];
            u[q] = hh[(size_t)s * 32 + lane];
        }
#pragma unroll
        for (int q = 0; q < 8; q++) {
            float2 f0 = __half22float2(*(half2*)&u[q].x);
            float2 f1 = __half22float2(*(half2*)&u[q].y);
            ax += f0.x; ay += f0.y; az += f1.x; aw += f1.y;
        }
    }
    for (; j < r1; j++) {
        int s = g_csrc[j];
        uint2 uu = hh[(size_t)s * 32 + lane];
        float2 f0 = __half22float2(*(half2*)&uu.x);
        float2 f1 = __half22float2(*(half2*)&uu.y);
        ax += f0.x; ay += f0.y; az += f1.x; aw += f1.y;
    }
    float inv = 1.f / fmaxf((float)(r1 - r0), 1.f);
    float4 o = make_float4(ax * inv, ay * inv, az * inv, aw * inv);
    *(float4*)(g_agg + (size_t)w * DG + (size_t)lane * 4) = o;
}

// ---------------------------------------------------------------------------
// Layer 1 output GEMM + relu, TF32 tensor cores (mma.sync m16n8k8).
// out[m, :] = relu( [agg | h][m, :] @ [Wl ; Wr] + b1 ),  K = 256.
// Block: 128 threads = 4 warps (2x2). Tile M=64, N=128. K chunked by 32.
// ---------------------------------------------------------------------------
__device__ __forceinline__ float to_tf32(float x) {
    float r;
    asm("cvt.rna.tf32.f32 %0, %1;" : "=f"(r) : "f"(x));
    return r;
}

#define KB 32
__global__ __launch_bounds__(128) void out_kernel(
    const float* __restrict__ Wl, const float* __restrict__ Wr,
    const float* __restrict__ bias, float* __restrict__ out, int n) {
    __shared__ float sA[64][36];
    __shared__ float sB[KB][136];

    int tid = threadIdx.x;
    int wid = tid >> 5;
    int lane = tid & 31;
    int wm = wid >> 1;
    int wn = wid & 1;
    int gid = lane >> 2;
    int tg = lane & 3;
    int n0 = blockIdx.x * 64;

    float acc[2][8][4];
#pragma unroll
    for (int mt = 0; mt < 2; mt++)
#pragma unroll
        for (int nt = 0; nt < 8; nt++)
#pragma unroll
            for (int i = 0; i < 4; i++) acc[mt][nt][i] = 0.f;

    int arow = tid >> 1;
    int akp = (tid & 1) * 16;
    bool aact = (n0 + arow) < n;
    int bk = tid >> 2;
    int bnb = (tid & 3) * 32;

    for (int kc = 0; kc < 2 * DG; kc += KB) {
        __syncthreads();
        {
            const float* src = (kc < DG) ? g_agg : g_h;
            int kadj = kc & (DG - 1);
#pragma unroll
            for (int q = 0; q < 4; q++) {
                float4 v = make_float4(0.f, 0.f, 0.f, 0.f);
                if (aact)
                    v = *(const float4*)&src[(size_t)(n0 + arow) * DG + kadj + akp + q * 4];
                int kk = akp + q * 4;
                sA[arow][kk + 0] = to_tf32(v.x);
                sA[arow][kk + 1] = to_tf32(v.y);
                sA[arow][kk + 2] = to_tf32(v.z);
                sA[arow][kk + 3] = to_tf32(v.w);
            }
        }
        {
            const float* W = (kc < DG) ? Wl : Wr;
            int kadj = (kc & (DG - 1)) + bk;
#pragma unroll
            for (int q = 0; q < 8; q++) {
                float4 v = *(const float4*)&W[(size_t)kadj * DG + bnb + q * 4];
                int nn = bnb + q * 4;
                sB[bk][nn + 0] = to_tf32(v.x);
                sB[bk][nn + 1] = to_tf32(v.y);
                sB[bk][nn + 2] = to_tf32(v.z);
                sB[bk][nn + 3] = to_tf32(v.w);
            }
        }
        __syncthreads();

#pragma unroll
        for (int ks = 0; ks < KB; ks += 8) {
            uint32_t bf[8][2];
#pragma unroll
            for (int nt = 0; nt < 8; nt++) {
                int ncol = wn * 64 + nt * 8 + gid;
                bf[nt][0] = __float_as_uint(sB[ks + tg][ncol]);
                bf[nt][1] = __float_as_uint(sB[ks + tg + 4][ncol]);
            }
#pragma unroll
            for (int mt = 0; mt < 2; mt++) {
                int r = wm * 32 + mt * 16 + gid;
                uint32_t af0 = __float_as_uint(sA[r][ks + tg]);
                uint32_t af1 = __float_as_uint(sA[r + 8][ks + tg]);
                uint32_t af2 = __float_as_uint(sA[r][ks + tg + 4]);
                uint32_t af3 = __float_as_uint(sA[r + 8][ks + tg + 4]);
#pragma unroll
                for (int nt = 0; nt < 8; nt++) {
                    asm volatile(
                        "mma.sync.aligned.m16n8k8.row.col.f32.tf32.tf32.f32 "
                        "{%0,%1,%2,%3}, {%4,%5,%6,%7}, {%8,%9}, {%0,%1,%2,%3};"
                        : "+f"(acc[mt][nt][0]), "+f"(acc[mt][nt][1]),
                          "+f"(acc[mt][nt][2]), "+f"(acc[mt][nt][3])
                        : "r"(af0), "r"(af1), "r"(af2), "r"(af3),
                          "r"(bf[nt][0]), "r"(bf[nt][1]));
                }
            }
        }
    }

#pragma unroll
    for (int nt = 0; nt < 8; nt++) {
        int col = wn * 64 + nt * 8 + 2 * tg;
        float2 bv = *(const float2*)&bias[col];
#pragma unroll
        for (int mt = 0; mt < 2; mt++) {
            int row = n0 + wm * 32 + mt * 16 + gid;
            if (row < n) {
                float2 o;
                o.x = fmaxf(acc[mt][nt][0] + bv.x, 0.f);
                o.y = fmaxf(acc[mt][nt][1] + bv.y, 0.f);
                *(float2*)&out[(size_t)row * DG + col] = o;
            }
            if (row + 8 < n) {
                float2 o;
                o.x = fmaxf(acc[mt][nt][2] + bv.x, 0.f);
                o.y = fmaxf(acc[mt][nt][3] + bv.y, 0.f);
                *(float2*)&out[(size_t)(row + 8) * DG + col] = o;
            }
        }
    }
}

// ---------------------------------------------------------------------------
extern "C" void kernel_launch(void* const* d_in, const int* in_sizes, int n_in,
                              void* d_out, int out_size) {
    const float* x   = (const float*)d_in[0];
    const int*   ei  = (const int*)d_in[1];
    const float* Wl0 = (const float*)d_in[2];
    const float* Wr0 = (const float*)d_in[3];
    const float* b0  = (const float*)d_in[4];
    const float* Wl1 = (const float*)d_in[5];
    const float* Wr1 = (const float*)d_in[6];
    const float* b1  = (const float*)d_in[7];
    const float* g   = (const float*)d_in[8];
    const float* be  = (const float*)d_in[9];
    float* out = (float*)d_out;

    int n  = in_sizes[0] / 3;
    int nE = in_sizes[1] / 2;

    zero_deg_kernel<<<(n + 255) / 256, 256>>>(n);
    hist_kernel<<<(nE + 255) / 256, 256>>>(ei, nE);
    scan_kernel<<<1, 1024>>>(n);
    fill_kernel<<<(nE + 255) / 256, 256>>>(ei, nE);
    int blocks = (n * 32 + 255) / 256;
    layer0_kernel<<<blocks, 256>>>(x, Wl0, Wr0, b0, g, be, n);
    agg_kernel<<<blocks, 256>>>(n);
    out_kernel<<<(n + 63) / 64, 128>>>(Wl1, Wr1, b1, out, n);
}

// round 7
// speedup vs baseline: 1.5872x; 1.3175x over previous
#include <cuda_runtime.h>
#include <cuda_fp16.h>
#include <cstdint>

#define DG 128
#define MAXN 100000
#define MAXE 1600000

// Scratch (device globals — no allocation allowed).
__device__ int g_deg[MAXN];
__device__ int g_rowptr[MAXN + 1];
__device__ int g_cursor[MAXN];
__device__ int g_csrc[MAXE];
__device__ __align__(16) __half g_hh[MAXN * DG];    // h after layer0+LN (fp16)
__device__ __align__(16) __half g_aggh[MAXN * DG];  // layer1 mean-agg (fp16)
__device__ __align__(16) __half g_wh[2 * DG * DG];  // [n][k] fp16 fused weights

// ---------------------------------------------------------------------------
// CSR build: zero deg -> histogram -> 1-block scan -> fill (sorted by dst)
// ---------------------------------------------------------------------------
__global__ void zero_deg_kernel(int n) {
    int i = blockIdx.x * blockDim.x + threadIdx.x;
    if (i < n) g_deg[i] = 0;
}

__global__ void hist_kernel(const int* __restrict__ ei, int nE) {
    int e = blockIdx.x * blockDim.x + threadIdx.x;
    if (e < nE) atomicAdd(&g_deg[ei[nE + e]], 1);
}

__global__ __launch_bounds__(1024) void scan_kernel(int n) {
    int t = threadIdx.x;
    int lane = t & 31, wid = t >> 5;
    int per = (n + 1023) >> 10;
    int start = t * per;
    int end = start + per; if (end > n) end = n;
    int s = 0;
    for (int i = start; i < end; i++) s += g_deg[i];
    int val = s;
#pragma unroll
    for (int o = 1; o < 32; o <<= 1) {
        int u = __shfl_up_sync(0xffffffffu, val, o);
        if (lane >= o) val += u;
    }
    __shared__ int wsum[32];
    if (lane == 31) wsum[wid] = val;
    __syncthreads();
    if (wid == 0) {
        int w = wsum[lane];
#pragma unroll
        for (int o = 1; o < 32; o <<= 1) {
            int u = __shfl_up_sync(0xffffffffu, w, o);
            if (lane >= o) w += u;
        }
        wsum[lane] = w;
    }
    __syncthreads();
    int base = val - s + (wid ? wsum[wid - 1] : 0);
    int run = base;
    for (int i = start; i < end; i++) {
        g_rowptr[i] = run;
        g_cursor[i] = run;
        run += g_deg[i];
    }
    if (end == n) g_rowptr[n] = run;
}

__global__ void fill_kernel(const int* __restrict__ ei, int nE) {
    int e = blockIdx.x * blockDim.x + threadIdx.x;
    if (e >= nE) return;
    int s = ei[e];
    int d = ei[nE + e];
    int pos = atomicAdd(&g_cursor[d], 1);
    g_csrc[pos] = s;
}

// ---------------------------------------------------------------------------
// Weight fuse+convert: g_wh[n][k] = fp16( k<128 ? Wl1[k][n] : Wr1[k-128][n] )
// ---------------------------------------------------------------------------
__global__ void convw_kernel(const float* __restrict__ Wl,
                             const float* __restrict__ Wr) {
    int t = blockIdx.x * blockDim.x + threadIdx.x;   // 0..32767
    int k = t >> 7, nn = t & 127;
    float v = (k < DG) ? Wl[k * DG + nn] : Wr[(k - DG) * DG + nn];
    g_wh[nn * 2 * DG + k] = __float2half_rn(v);
}

// ---------------------------------------------------------------------------
// Layer 0 (fused): warp per node. Gather x[src] (mean), 3->128 linear + bias
// + ReLU + LayerNorm, all in-warp. Emits h in fp16.
// ---------------------------------------------------------------------------
__device__ __forceinline__ float warp_sum(float v) {
#pragma unroll
    for (int o = 16; o; o >>= 1) v += __shfl_xor_sync(0xffffffffu, v, o);
    return v;
}

__global__ __launch_bounds__(256) void layer0_kernel(
    const float* __restrict__ x, const float* __restrict__ Wl,
    const float* __restrict__ Wr, const float* __restrict__ b,
    const float* __restrict__ g, const float* __restrict__ be, int n) {
    int w = (blockIdx.x * blockDim.x + threadIdx.x) >> 5;
    if (w >= n) return;
    int lane = threadIdx.x & 31;
    int r0 = g_rowptr[w], r1 = g_rowptr[w + 1];

    float a0 = 0.f, a1 = 0.f, a2 = 0.f;
    for (int j = r0 + lane; j < r1; j += 32) {
        int s = g_csrc[j];
        a0 += x[3 * s];
        a1 += x[3 * s + 1];
        a2 += x[3 * s + 2];
    }
    a0 = warp_sum(a0); a1 = warp_sum(a1); a2 = warp_sum(a2);
    float inv = 1.f / fmaxf((float)(r1 - r0), 1.f);
    a0 *= inv; a1 *= inv; a2 *= inv;

    float x0 = x[3 * w], x1 = x[3 * w + 1], x2 = x[3 * w + 2];

    int col = lane * 4;
    float4 wl0 = *(const float4*)&Wl[0 * DG + col];
    float4 wl1 = *(const float4*)&Wl[1 * DG + col];
    float4 wl2 = *(const float4*)&Wl[2 * DG + col];
    float4 wr0 = *(const float4*)&Wr[0 * DG + col];
    float4 wr1 = *(const float4*)&Wr[1 * DG + col];
    float4 wr2 = *(const float4*)&Wr[2 * DG + col];
    float4 bv  = *(const float4*)&b[col];

    float v0 = bv.x + a0 * wl0.x + a1 * wl1.x + a2 * wl2.x + x0 * wr0.x + x1 * wr1.x + x2 * wr2.x;
    float v1 = bv.y + a0 * wl0.y + a1 * wl1.y + a2 * wl2.y + x0 * wr0.y + x1 * wr1.y + x2 * wr2.y;
    float v2 = bv.z + a0 * wl0.z + a1 * wl1.z + a2 * wl2.z + x0 * wr0.z + x1 * wr1.z + x2 * wr2.z;
    float v3 = bv.w + a0 * wl0.w + a1 * wl1.w + a2 * wl2.w + x0 * wr0.w + x1 * wr1.w + x2 * wr2.w;
    v0 = fmaxf(v0, 0.f); v1 = fmaxf(v1, 0.f); v2 = fmaxf(v2, 0.f); v3 = fmaxf(v3, 0.f);

    float mu = warp_sum(v0 + v1 + v2 + v3) * (1.f / DG);
    float d0 = v0 - mu, d1 = v1 - mu, d2 = v2 - mu, d3 = v3 - mu;
    float var = warp_sum(d0 * d0 + d1 * d1 + d2 * d2 + d3 * d3) * (1.f / DG);
    float rs = rsqrtf(var + 1e-5f);

    float4 gv = *(const float4*)&g[col];
    float4 bev = *(const float4*)&be[col];
    half2 p0 = __floats2half2_rn(d0 * rs * gv.x + bev.x, d1 * rs * gv.y + bev.y);
    half2 p1 = __floats2half2_rn(d2 * rs * gv.z + bev.z, d3 * rs * gv.w + bev.w);
    uint2 pk = make_uint2(*(uint32_t*)&p0, *(uint32_t*)&p1);
    *(uint2*)(g_hh + (size_t)w * DG + col) = pk;
}

// ---------------------------------------------------------------------------
// Layer 1 aggregation: warp per dst node, fp16 gather, fp32 accumulate,
// 8-way unroll. inv_deg applied; result stored fp16.
// ---------------------------------------------------------------------------
__global__ __launch_bounds__(256) void agg_kernel(int n) {
    int w = (blockIdx.x * blockDim.x + threadIdx.x) >> 5;
    if (w >= n) return;
    int lane = threadIdx.x & 31;
    int r0 = g_rowptr[w], r1 = g_rowptr[w + 1];
    const uint2* hh = (const uint2*)g_hh;   // 32 uint2 per node row

    float ax = 0.f, ay = 0.f, az = 0.f, aw = 0.f;
    int j = r0;
    for (; j + 8 <= r1; j += 8) {
        uint2 u[8];
#pragma unroll
        for (int q = 0; q < 8; q++) {
            int s = g_csrc[j + q];
            u[q] = hh[(size_t)s * 32 + lane];
        }
#pragma unroll
        for (int q = 0; q < 8; q++) {
            float2 f0 = __half22float2(*(half2*)&u[q].x);
            float2 f1 = __half22float2(*(half2*)&u[q].y);
            ax += f0.x; ay += f0.y; az += f1.x; aw += f1.y;
        }
    }
    for (; j < r1; j++) {
        int s = g_csrc[j];
        uint2 uu = hh[(size_t)s * 32 + lane];
        float2 f0 = __half22float2(*(half2*)&uu.x);
        float2 f1 = __half22float2(*(half2*)&uu.y);
        ax += f0.x; ay += f0.y; az += f1.x; aw += f1.y;
    }
    float inv = 1.f / fmaxf((float)(r1 - r0), 1.f);
    half2 p0 = __floats2half2_rn(ax * inv, ay * inv);
    half2 p1 = __floats2half2_rn(az * inv, aw * inv);
    uint2 pk = make_uint2(*(uint32_t*)&p0, *(uint32_t*)&p1);
    *(uint2*)(g_aggh + (size_t)w * DG + (size_t)lane * 4) = pk;
}

// ---------------------------------------------------------------------------
// Layer 1 output GEMM + relu, fp16 tensor cores (mma.sync m16n8k16, f32 acc).
// out[m, :] = relu( [agg | h][m, :] @ Wfused + b1 ),  K = 256.
// Block: 256 threads = 8 warps (4x2). Tile M=128, N=128. K chunked by 32.
// ---------------------------------------------------------------------------
#define KB 32
#define ASTR 40   // smem row stride in halfs (20 words -> conflict-free frags)
__global__ __launch_bounds__(256) void out_kernel(
    const float* __restrict__ bias, float* __restrict__ out, int n) {
    __shared__ __align__(16) __half sA[128][ASTR];
    __shared__ __align__(16) __half sB[128][ASTR];   // [n][k-chunk]

    int tid = threadIdx.x;
    int wid = tid >> 5;
    int lane = tid & 31;
    int wm = wid >> 1;        // 0..3 : rows wm*32 .. +31
    int wn = wid & 1;         // 0..1 : cols wn*64 .. +63
    int gid = lane >> 2;      // 0..7
    int tg = lane & 3;        // 0..3
    int n0 = blockIdx.x * 128;

    float acc[2][8][4];
#pragma unroll
    for (int mt = 0; mt < 2; mt++)
#pragma unroll
        for (int nt = 0; nt < 8; nt++)
#pragma unroll
            for (int i = 0; i < 4; i++) acc[mt][nt][i] = 0.f;

    for (int kc = 0; kc < 2 * DG; kc += KB) {
        __syncthreads();
        // stage A: 128 rows x 32 halfs (4 uint4 per row), 2 uint4 per thread
        {
            const __half* src = (kc < DG) ? g_aggh : g_hh;
            int ka = kc & (DG - 1);
#pragma unroll
            for (int q = 0; q < 2; q++) {
                int idx = tid + q * 256;       // 0..511
                int r = idx >> 2;              // 0..127
                int part = idx & 3;            // 0..3 (8 halfs each)
                uint4 v = make_uint4(0, 0, 0, 0);
                if (n0 + r < n)
                    v = *(const uint4*)(src + (size_t)(n0 + r) * DG + ka + part * 8);
                *(uint4*)&sA[r][part * 8] = v;
            }
        }
        // stage B: 128 n-rows x 32 halfs from g_wh[n][kc..kc+31]
        {
#pragma unroll
            for (int q = 0; q < 2; q++) {
                int idx = tid + q * 256;
                int r = idx >> 2;
                int part = idx & 3;
                uint4 v = *(const uint4*)(g_wh + (size_t)r * 2 * DG + kc + part * 8);
                *(uint4*)&sB[r][part * 8] = v;
            }
        }
        __syncthreads();

#pragma unroll
        for (int ks = 0; ks < 2; ks++) {       // two k16 steps per chunk
            int ko = ks * 16;
            uint32_t bf[8][2];
#pragma unroll
            for (int nt = 0; nt < 8; nt++) {
                int ncol = wn * 64 + nt * 8 + gid;
                bf[nt][0] = *(uint32_t*)&sB[ncol][ko + 2 * tg];
                bf[nt][1] = *(uint32_t*)&sB[ncol][ko + 2 * tg + 8];
            }
#pragma unroll
            for (int mt = 0; mt < 2; mt++) {
                int r = wm * 32 + mt * 16 + gid;
                uint32_t a0 = *(uint32_t*)&sA[r][ko + 2 * tg];
                uint32_t a1 = *(uint32_t*)&sA[r + 8][ko + 2 * tg];
                uint32_t a2 = *(uint32_t*)&sA[r][ko + 2 * tg + 8];
                uint32_t a3 = *(uint32_t*)&sA[r + 8][ko + 2 * tg + 8];
#pragma unroll
                for (int nt = 0; nt < 8; nt++) {
                    asm volatile(
                        "mma.sync.aligned.m16n8k16.row.col.f32.f16.f16.f32 "
                        "{%0,%1,%2,%3}, {%4,%5,%6,%7}, {%8,%9}, {%0,%1,%2,%3};"
                        : "+f"(acc[mt][nt][0]), "+f"(acc[mt][nt][1]),
                          "+f"(acc[mt][nt][2]), "+f"(acc[mt][nt][3])
                        : "r"(a0), "r"(a1), "r"(a2), "r"(a3),
                          "r"(bf[nt][0]), "r"(bf[nt][1]));
                }
            }
        }
    }

    // epilogue: bias + relu, float2 stores (c0/c1 adjacent cols)
#pragma unroll
    for (int nt = 0; nt < 8; nt++) {
        int col = wn * 64 + nt * 8 + 2 * tg;
        float2 bv = *(const float2*)&bias[col];
#pragma unroll
        for (int mt = 0; mt < 2; mt++) {
            int row = n0 + wm * 32 + mt * 16 + gid;
            if (row < n) {
                float2 o;
                o.x = fmaxf(acc[mt][nt][0] + bv.x, 0.f);
                o.y = fmaxf(acc[mt][nt][1] + bv.y, 0.f);
                *(float2*)&out[(size_t)row * DG + col] = o;
            }
            if (row + 8 < n) {
                float2 o;
                o.x = fmaxf(acc[mt][nt][2] + bv.x, 0.f);
                o.y = fmaxf(acc[mt][nt][3] + bv.y, 0.f);
                *(float2*)&out[(size_t)(row + 8) * DG + col] = o;
            }
        }
    }
}

// ---------------------------------------------------------------------------
extern "C" void kernel_launch(void* const* d_in, const int* in_sizes, int n_in,
                              void* d_out, int out_size) {
    const float* x   = (const float*)d_in[0];
    const int*   ei  = (const int*)d_in[1];
    const float* Wl0 = (const float*)d_in[2];
    const float* Wr0 = (const float*)d_in[3];
    const float* b0  = (const float*)d_in[4];
    const float* Wl1 = (const float*)d_in[5];
    const float* Wr1 = (const float*)d_in[6];
    const float* b1  = (const float*)d_in[7];
    const float* g   = (const float*)d_in[8];
    const float* be  = (const float*)d_in[9];
    float* out = (float*)d_out;

    int n  = in_sizes[0] / 3;
    int nE = in_sizes[1] / 2;

    zero_deg_kernel<<<(n + 255) / 256, 256>>>(n);
    convw_kernel<<<(2 * DG * DG) / 256, 256>>>(Wl1, Wr1);
    hist_kernel<<<(nE + 255) / 256, 256>>>(ei, nE);
    scan_kernel<<<1, 1024>>>(n);
    fill_kernel<<<(nE + 255) / 256, 256>>>(ei, nE);
    int blocks = (n * 32 + 255) / 256;
    layer0_kernel<<<blocks, 256>>>(x, Wl0, Wr0, b0, g, be, n);
    agg_kernel<<<blocks, 256>>>(n);
    out_kernel<<<(n + 127) / 128, 256>>>(b1, out, n);
}

// round 8
// speedup vs baseline: 3.1140x; 1.9619x over previous
#include <cuda_runtime.h>
#include <cuda_fp16.h>
#include <cstdint>

#define DG 128
#define MAXN 100000
#define MAXE 1600000
#define SCB 1024                     // elements per scan chunk
#define MAXB ((MAXN + SCB - 1) / SCB)

// Scratch (device globals — no allocation allowed).
__device__ int g_deg[MAXN];
__device__ int g_rowptr[MAXN + 1];
__device__ int g_cursor[MAXN];
__device__ int g_csrc[MAXE];
__device__ int g_bsum[MAXB];
__device__ int g_boff[MAXB];
__device__ __align__(16) __half g_hh[MAXN * DG];    // h after layer0+LN (fp16)
__device__ __align__(16) __half g_aggh[MAXN * DG];  // layer1 mean-agg (fp16)
__device__ __align__(16) __half g_wh[2 * DG * DG];  // [n][k] fp16 fused weights

// ---------------------------------------------------------------------------
// CSR build: zero deg -> histogram -> 3-phase parallel scan -> fill
// ---------------------------------------------------------------------------
__global__ void zero_deg_kernel(int n) {
    int i = blockIdx.x * blockDim.x + threadIdx.x;
    if (i < n) g_deg[i] = 0;
}

__global__ void hist_kernel(const int* __restrict__ ei, int nE) {
    int e = blockIdx.x * blockDim.x + threadIdx.x;
    if (e < nE) atomicAdd(&g_deg[ei[nE + e]], 1);
}

// Phase 1: per-chunk sums. Grid = nb blocks of 256; chunk = 1024 elems.
__global__ __launch_bounds__(256) void bsum_kernel(int n) {
    int base = blockIdx.x * SCB;
    int t = threadIdx.x;
    int s = 0;
#pragma unroll
    for (int q = 0; q < 4; q++) {
        int i = base + t + q * 256;
        if (i < n) s += g_deg[i];
    }
#pragma unroll
    for (int o = 16; o; o >>= 1) s += __shfl_xor_sync(0xffffffffu, s, o);
    __shared__ int wt[8];
    if ((t & 31) == 0) wt[t >> 5] = s;
    __syncthreads();
    if (t == 0) {
        int tot = 0;
#pragma unroll
        for (int i = 0; i < 8; i++) tot += wt[i];
        g_bsum[blockIdx.x] = tot;
    }
}

// Phase 2: scan block sums (nb <= 128). One block of 128 threads.
__global__ __launch_bounds__(128) void bscan_kernel(int nb, int n) {
    int t = threadIdx.x;
    int lane = t & 31, wid = t >> 5;
    int v = (t < nb) ? g_bsum[t] : 0;
    int incl = v;
#pragma unroll
    for (int o = 1; o < 32; o <<= 1) {
        int u = __shfl_up_sync(0xffffffffu, incl, o);
        if (lane >= o) incl += u;
    }
    __shared__ int wt[4];
    if (lane == 31) wt[wid] = incl;
    __syncthreads();
    if (t == 0) {
        int run = 0;
#pragma unroll
        for (int i = 0; i < 4; i++) { int u = wt[i]; wt[i] = run; run += u; }
    }
    __syncthreads();
    incl += wt[wid];
    if (t < nb) g_boff[t] = incl - v;      // exclusive offset per chunk
    if (t == nb - 1) g_rowptr[n] = incl;   // grand total
}

// Phase 3: in-chunk exclusive scan + chunk offset -> rowptr & cursor.
__global__ __launch_bounds__(256) void scan_chunk_kernel(int n) {
    int base = blockIdx.x * SCB;
    int t = threadIdx.x;
    int i0 = base + t * 4;
    int d0 = (i0 + 0 < n) ? g_deg[i0 + 0] : 0;
    int d1 = (i0 + 1 < n) ? g_deg[i0 + 1] : 0;
    int d2 = (i0 + 2 < n) ? g_deg[i0 + 2] : 0;
    int d3 = (i0 + 3 < n) ? g_deg[i0 + 3] : 0;
    int s = d0 + d1 + d2 + d3;

    int lane = t & 31, wid = t >> 5;
    int incl = s;
#pragma unroll
    for (int o = 1; o < 32; o <<= 1) {
        int u = __shfl_up_sync(0xffffffffu, incl, o);
        if (lane >= o) incl += u;
    }
    __shared__ int wt[8];
    if (lane == 31) wt[wid] = incl;
    __syncthreads();
    if (t == 0) {
        int run = 0;
#pragma unroll
        for (int i = 0; i < 8; i++) { int u = wt[i]; wt[i] = run; run += u; }
    }
    __syncthreads();
    int run = incl - s + wt[wid] + g_boff[blockIdx.x];
    if (i0 + 0 < n) { g_rowptr[i0 + 0] = run; g_cursor[i0 + 0] = run; run += d0; }
    if (i0 + 1 < n) { g_rowptr[i0 + 1] = run; g_cursor[i0 + 1] = run; run += d1; }
    if (i0 + 2 < n) { g_rowptr[i0 + 2] = run; g_cursor[i0 + 2] = run; run += d2; }
    if (i0 + 3 < n) { g_rowptr[i0 + 3] = run; g_cursor[i0 + 3] = run; run += d3; }
}

__global__ void fill_kernel(const int* __restrict__ ei, int nE) {
    int e = blockIdx.x * blockDim.x + threadIdx.x;
    if (e >= nE) return;
    int s = ei[e];
    int d = ei[nE + e];
    int pos = atomicAdd(&g_cursor[d], 1);
    g_csrc[pos] = s;
}

// ---------------------------------------------------------------------------
// Weight fuse+convert: g_wh[n][k] = fp16( k<128 ? Wl1[k][n] : Wr1[k-128][n] )
// ---------------------------------------------------------------------------
__global__ void convw_kernel(const float* __restrict__ Wl,
                             const float* __restrict__ Wr) {
    int t = blockIdx.x * blockDim.x + threadIdx.x;
    int k = t >> 7, nn = t & 127;
    float v = (k < DG) ? Wl[k * DG + nn] : Wr[(k - DG) * DG + nn];
    g_wh[nn * 2 * DG + k] = __float2half_rn(v);
}

// ---------------------------------------------------------------------------
// Layer 0 (fused): warp per node. Gather x[src] (mean), 3->128 linear + bias
// + ReLU + LayerNorm, all in-warp. Emits h in fp16.
// ---------------------------------------------------------------------------
__device__ __forceinline__ float warp_sum(float v) {
#pragma unroll
    for (int o = 16; o; o >>= 1) v += __shfl_xor_sync(0xffffffffu, v, o);
    return v;
}

__global__ __launch_bounds__(256) void layer0_kernel(
    const float* __restrict__ x, const float* __restrict__ Wl,
    const float* __restrict__ Wr, const float* __restrict__ b,
    const float* __restrict__ g, const float* __restrict__ be, int n) {
    int w = (blockIdx.x * blockDim.x + threadIdx.x) >> 5;
    if (w >= n) return;
    int lane = threadIdx.x & 31;
    int r0 = g_rowptr[w], r1 = g_rowptr[w + 1];

    float a0 = 0.f, a1 = 0.f, a2 = 0.f;
    for (int j = r0 + lane; j < r1; j += 32) {
        int s = g_csrc[j];
        a0 += x[3 * s];
        a1 += x[3 * s + 1];
        a2 += x[3 * s + 2];
    }
    a0 = warp_sum(a0); a1 = warp_sum(a1); a2 = warp_sum(a2);
    float inv = 1.f / fmaxf((float)(r1 - r0), 1.f);
    a0 *= inv; a1 *= inv; a2 *= inv;

    float x0 = x[3 * w], x1 = x[3 * w + 1], x2 = x[3 * w + 2];

    int col = lane * 4;
    float4 wl0 = *(const float4*)&Wl[0 * DG + col];
    float4 wl1 = *(const float4*)&Wl[1 * DG + col];
    float4 wl2 = *(const float4*)&Wl[2 * DG + col];
    float4 wr0 = *(const float4*)&Wr[0 * DG + col];
    float4 wr1 = *(const float4*)&Wr[1 * DG + col];
    float4 wr2 = *(const float4*)&Wr[2 * DG + col];
    float4 bv  = *(const float4*)&b[col];

    float v0 = bv.x + a0 * wl0.x + a1 * wl1.x + a2 * wl2.x + x0 * wr0.x + x1 * wr1.x + x2 * wr2.x;
    float v1 = bv.y + a0 * wl0.y + a1 * wl1.y + a2 * wl2.y + x0 * wr0.y + x1 * wr1.y + x2 * wr2.y;
    float v2 = bv.z + a0 * wl0.z + a1 * wl1.z + a2 * wl2.z + x0 * wr0.z + x1 * wr1.z + x2 * wr2.z;
    float v3 = bv.w + a0 * wl0.w + a1 * wl1.w + a2 * wl2.w + x0 * wr0.w + x1 * wr1.w + x2 * wr2.w;
    v0 = fmaxf(v0, 0.f); v1 = fmaxf(v1, 0.f); v2 = fmaxf(v2, 0.f); v3 = fmaxf(v3, 0.f);

    float mu = warp_sum(v0 + v1 + v2 + v3) * (1.f / DG);
    float d0 = v0 - mu, d1 = v1 - mu, d2 = v2 - mu, d3 = v3 - mu;
    float var = warp_sum(d0 * d0 + d1 * d1 + d2 * d2 + d3 * d3) * (1.f / DG);
    float rs = rsqrtf(var + 1e-5f);

    float4 gv = *(const float4*)&g[col];
    float4 bev = *(const float4*)&be[col];
    half2 p0 = __floats2half2_rn(d0 * rs * gv.x + bev.x, d1 * rs * gv.y + bev.y);
    half2 p1 = __floats2half2_rn(d2 * rs * gv.z + bev.z, d3 * rs * gv.w + bev.w);
    uint2 pk = make_uint2(*(uint32_t*)&p0, *(uint32_t*)&p1);
    *(uint2*)(g_hh + (size_t)w * DG + col) = pk;
}

// ---------------------------------------------------------------------------
// Layer 1 aggregation: warp per dst node, fp16 gather, fp32 accumulate,
// 8-way unroll. inv_deg applied; result stored fp16.
// ---------------------------------------------------------------------------
__global__ __launch_bounds__(256) void agg_kernel(int n) {
    int w = (blockIdx.x * blockDim.x + threadIdx.x) >> 5;
    if (w >= n) return;
    int lane = threadIdx.x & 31;
    int r0 = g_rowptr[w], r1 = g_rowptr[w + 1];
    const uint2* hh = (const uint2*)g_hh;

    float ax = 0.f, ay = 0.f, az = 0.f, aw = 0.f;
    int j = r0;
    for (; j + 8 <= r1; j += 8) {
        uint2 u[8];
#pragma unroll
        for (int q = 0; q < 8; q++) {
            int s = g_csrc[j + q];
            u[q] = hh[(size_t)s * 32 + lane];
        }
#pragma unroll
        for (int q = 0; q < 8; q++) {
            float2 f0 = __half22float2(*(half2*)&u[q].x);
            float2 f1 = __half22float2(*(half2*)&u[q].y);
            ax += f0.x; ay += f0.y; az += f1.x; aw += f1.y;
        }
    }
    for (; j < r1; j++) {
        int s = g_csrc[j];
        uint2 uu = hh[(size_t)s * 32 + lane];
        float2 f0 = __half22float2(*(half2*)&uu.x);
        float2 f1 = __half22float2(*(half2*)&uu.y);
        ax += f0.x; ay += f0.y; az += f1.x; aw += f1.y;
    }
    float inv = 1.f / fmaxf((float)(r1 - r0), 1.f);
    half2 p0 = __floats2half2_rn(ax * inv, ay * inv);
    half2 p1 = __floats2half2_rn(az * inv, aw * inv);
    uint2 pk = make_uint2(*(uint32_t*)&p0, *(uint32_t*)&p1);
    *(uint2*)(g_aggh + (size_t)w * DG + (size_t)lane * 4) = pk;
}

// ---------------------------------------------------------------------------
// Layer 1 output GEMM + relu, fp16 tensor cores (mma.sync m16n8k16, f32 acc).
// Block: 256 threads = 8 warps (4x2). Tile M=128, N=128. K chunked by 32.
// ---------------------------------------------------------------------------
#define KB 32
#define ASTR 40
__global__ __launch_bounds__(256) void out_kernel(
    const float* __restrict__ bias, float* __restrict__ out, int n) {
    __shared__ __align__(16) __half sA[128][ASTR];
    __shared__ __align__(16) __half sB[128][ASTR];

    int tid = threadIdx.x;
    int wid = tid >> 5;
    int lane = tid & 31;
    int wm = wid >> 1;
    int wn = wid & 1;
    int gid = lane >> 2;
    int tg = lane & 3;
    int n0 = blockIdx.x * 128;

    float acc[2][8][4];
#pragma unroll
    for (int mt = 0; mt < 2; mt++)
#pragma unroll
        for (int nt = 0; nt < 8; nt++)
#pragma unroll
            for (int i = 0; i < 4; i++) acc[mt][nt][i] = 0.f;

    for (int kc = 0; kc < 2 * DG; kc += KB) {
        __syncthreads();
        {
            const __half* src = (kc < DG) ? g_aggh : g_hh;
            int ka = kc & (DG - 1);
#pragma unroll
            for (int q = 0; q < 2; q++) {
                int idx = tid + q * 256;
                int r = idx >> 2;
                int part = idx & 3;
                uint4 v = make_uint4(0, 0, 0, 0);
                if (n0 + r < n)
                    v = *(const uint4*)(src + (size_t)(n0 + r) * DG + ka + part * 8);
                *(uint4*)&sA[r][part * 8] = v;
            }
        }
        {
#pragma unroll
            for (int q = 0; q < 2; q++) {
                int idx = tid + q * 256;
                int r = idx >> 2;
                int part = idx & 3;
                uint4 v = *(const uint4*)(g_wh + (size_t)r * 2 * DG + kc + part * 8);
                *(uint4*)&sB[r][part * 8] = v;
            }
        }
        __syncthreads();

#pragma unroll
        for (int ks = 0; ks < 2; ks++) {
            int ko = ks * 16;
            uint32_t bf[8][2];
#pragma unroll
            for (int nt = 0; nt < 8; nt++) {
                int ncol = wn * 64 + nt * 8 + gid;
                bf[nt][0] = *(uint32_t*)&sB[ncol][ko + 2 * tg];
                bf[nt][1] = *(uint32_t*)&sB[ncol][ko + 2 * tg + 8];
            }
#pragma unroll
            for (int mt = 0; mt < 2; mt++) {
                int r = wm * 32 + mt * 16 + gid;
                uint32_t a0 = *(uint32_t*)&sA[r][ko + 2 * tg];
                uint32_t a1 = *(uint32_t*)&sA[r + 8][ko + 2 * tg];
                uint32_t a2 = *(uint32_t*)&sA[r][ko + 2 * tg + 8];
                uint32_t a3 = *(uint32_t*)&sA[r + 8][ko + 2 * tg + 8];
#pragma unroll
                for (int nt = 0; nt < 8; nt++) {
                    asm volatile(
                        "mma.sync.aligned.m16n8k16.row.col.f32.f16.f16.f32 "
                        "{%0,%1,%2,%3}, {%4,%5,%6,%7}, {%8,%9}, {%0,%1,%2,%3};"
                        : "+f"(acc[mt][nt][0]), "+f"(acc[mt][nt][1]),
                          "+f"(acc[mt][nt][2]), "+f"(acc[mt][nt][3])
                        : "r"(a0), "r"(a1), "r"(a2), "r"(a3),
                          "r"(bf[nt][0]), "r"(bf[nt][1]));
                }
            }
        }
    }

#pragma unroll
    for (int nt = 0; nt < 8; nt++) {
        int col = wn * 64 + nt * 8 + 2 * tg;
        float2 bv = *(const float2*)&bias[col];
#pragma unroll
        for (int mt = 0; mt < 2; mt++) {
            int row = n0 + wm * 32 + mt * 16 + gid;
            if (row < n) {
                float2 o;
                o.x = fmaxf(acc[mt][nt][0] + bv.x, 0.f);
                o.y = fmaxf(acc[mt][nt][1] + bv.y, 0.f);
                *(float2*)&out[(size_t)row * DG + col] = o;
            }
            if (row + 8 < n) {
                float2 o;
                o.x = fmaxf(acc[mt][nt][2] + bv.x, 0.f);
                o.y = fmaxf(acc[mt][nt][3] + bv.y, 0.f);
                *(float2*)&out[(size_t)(row + 8) * DG + col] = o;
            }
        }
    }
}

// ---------------------------------------------------------------------------
extern "C" void kernel_launch(void* const* d_in, const int* in_sizes, int n_in,
                              void* d_out, int out_size) {
    const float* x   = (const float*)d_in[0];
    const int*   ei  = (const int*)d_in[1];
    const float* Wl0 = (const float*)d_in[2];
    const float* Wr0 = (const float*)d_in[3];
    const float* b0  = (const float*)d_in[4];
    const float* Wl1 = (const float*)d_in[5];
    const float* Wr1 = (const float*)d_in[6];
    const float* b1  = (const float*)d_in[7];
    const float* g   = (const float*)d_in[8];
    const float* be  = (const float*)d_in[9];
    float* out = (float*)d_out;

    int n  = in_sizes[0] / 3;
    int nE = in_sizes[1] / 2;
    int nb = (n + SCB - 1) / SCB;

    zero_deg_kernel<<<(n + 255) / 256, 256>>>(n);
    convw_kernel<<<(2 * DG * DG) / 256, 256>>>(Wl1, Wr1);
    hist_kernel<<<(nE + 255) / 256, 256>>>(ei, nE);
    bsum_kernel<<<nb, 256>>>(n);
    bscan_kernel<<<1, 128>>>(nb, n);
    scan_chunk_kernel<<<nb, 256>>>(n);
    fill_kernel<<<(nE + 255) / 256, 256>>>(ei, nE);
    int blocks = (n * 32 + 255) / 256;
    layer0_kernel<<<blocks, 256>>>(x, Wl0, Wr0, b0, g, be, n);
    agg_kernel<<<blocks, 256>>>(n);
    out_kernel<<<(n + 127) / 128, 256>>>(b1, out, n);
}